// round 4
// baseline (speedup 1.0000x reference)
#include <cuda_runtime.h>

// out[b,c] = H @ x[b,c] @ H^T for 65536 independent 32x32 fp32 matrices.
// One warp per matrix, 8 warps/block. 8x4 register tile per thread with
// accumulators packed as f32x2 row-pairs -> fma.rn.f32x2 = 2 FMAs/instr.
// launch_bounds(256,3) caps regs (~85) so ~24 warps/SM hide LDS latency;
// R2 showed 2-mats/warp blew the register budget (116 regs, occ 23%).

#define S_DIM 32
#define STRIDE 36              // 32 + 4 pad floats: 16B-aligned rows, conflict-free
#define WARPS_PER_BLOCK 8
#define MATS_PER_BLOCK WARPS_PER_BLOCK
#define NTHREADS (WARPS_PER_BLOCK * 32)

typedef unsigned long long u64;

__device__ __forceinline__ void fma2(u64& d, u64 a, u64 b) {
    asm("fma.rn.f32x2 %0, %1, %2, %0;" : "+l"(d) : "l"(a), "l"(b));
}
__device__ __forceinline__ u64 splat2(float v) {
    u64 r;
    asm("mov.b64 %0, {%1, %1};" : "=l"(r) : "f"(v));
    return r;
}
__device__ __forceinline__ float2 unpack2(u64 u) {
    float2 f;
    asm("mov.b64 {%0, %1}, %2;" : "=f"(f.x), "=f"(f.y) : "l"(u));
    return f;
}

__global__ __launch_bounds__(NTHREADS, 3)
void dct2d_kernel(const float* __restrict__ x,
                  const float* __restrict__ H,
                  float* __restrict__ out,
                  int nMat)
{
    __shared__ __align__(16) float Ht[S_DIM * S_DIM];                    // Ht[k][i] = H[i][k]
    __shared__ __align__(16) float buf[MATS_PER_BLOCK][S_DIM * STRIDE];  // X, then T^T

    const int tid = threadIdx.x;

    // Build H^T once per block.
    #pragma unroll
    for (int e = tid; e < S_DIM * S_DIM; e += NTHREADS) {
        int i = e >> 5;
        int k = e & 31;
        Ht[k * S_DIM + i] = H[e];
    }
    __syncthreads();

    const int warp = tid >> 5;
    const int lane = tid & 31;
    const int m = blockIdx.x * WARPS_PER_BLOCK + warp;
    if (m >= nMat) return;

    float* Xs = buf[warp];
    const float4* __restrict__ src =
        reinterpret_cast<const float4*>(x + (size_t)m * (S_DIM * S_DIM));

    // ---- load X[32][32] into padded smem (coalesced float4) ----
    #pragma unroll
    for (int q = 0; q < 8; q++) {
        int f   = lane + 32 * q;
        int row = f >> 3;
        int c4  = f & 7;
        *reinterpret_cast<float4*>(&Xs[row * STRIDE + c4 * 4]) = src[f];
    }
    __syncwarp();

    const int ti = lane >> 3;   // rows ti*8 .. ti*8+7
    const int tj = lane & 7;    // cols tj*4 .. tj*4+3

    // acc[p][c] packs rows (ti*8+2p, ti*8+2p+1) at column tj*4+c
    u64 acc[4][4];
    #pragma unroll
    for (int p = 0; p < 4; p++)
        #pragma unroll
        for (int c = 0; c < 4; c++) acc[p][c] = 0ull;

    // ---- stage 1: T[i][j] = sum_k Ht[k][i] * X[k][j] ----
    #pragma unroll 8
    for (int k = 0; k < S_DIM; k++) {
        const ulonglong2* ap =
            reinterpret_cast<const ulonglong2*>(&Ht[k * S_DIM + ti * 8]);
        ulonglong2 aA = ap[0], aB = ap[1];
        u64 a[4] = {aA.x, aA.y, aB.x, aB.y};

        float4 b4 = *reinterpret_cast<const float4*>(&Xs[k * STRIDE + tj * 4]);
        u64 bb[4] = {splat2(b4.x), splat2(b4.y), splat2(b4.z), splat2(b4.w)};

        #pragma unroll
        for (int p = 0; p < 4; p++)
            #pragma unroll
            for (int c = 0; c < 4; c++)
                fma2(acc[p][c], a[p], bb[c]);
    }
    __syncwarp();

    // ---- write T transposed back: Tt[j][i] = T[i][j] ----
    #pragma unroll
    for (int c = 0; c < 4; c++) {
        int row = tj * 4 + c;
        float2 f0 = unpack2(acc[0][c]), f1 = unpack2(acc[1][c]);
        float2 f2 = unpack2(acc[2][c]), f3 = unpack2(acc[3][c]);
        *reinterpret_cast<float4*>(&Xs[row * STRIDE + ti * 8]) =
            make_float4(f0.x, f0.y, f1.x, f1.y);
        *reinterpret_cast<float4*>(&Xs[row * STRIDE + ti * 8 + 4]) =
            make_float4(f2.x, f2.y, f3.x, f3.y);
    }
    __syncwarp();

    #pragma unroll
    for (int p = 0; p < 4; p++)
        #pragma unroll
        for (int c = 0; c < 4; c++) acc[p][c] = 0ull;

    // ---- stage 2: Out[i][l] = sum_k Tt[k][i] * Ht[k][l] ----
    #pragma unroll 8
    for (int k = 0; k < S_DIM; k++) {
        const ulonglong2* ap =
            reinterpret_cast<const ulonglong2*>(&Xs[k * STRIDE + ti * 8]);
        ulonglong2 aA = ap[0], aB = ap[1];
        u64 a[4] = {aA.x, aA.y, aB.x, aB.y};

        float4 b4 = *reinterpret_cast<const float4*>(&Ht[k * S_DIM + tj * 4]);
        u64 bb[4] = {splat2(b4.x), splat2(b4.y), splat2(b4.z), splat2(b4.w)};

        #pragma unroll
        for (int p = 0; p < 4; p++)
            #pragma unroll
            for (int c = 0; c < 4; c++)
                fma2(acc[p][c], a[p], bb[c]);
    }

    // ---- store Out[32][32] (coalesced float4) ----
    float* __restrict__ dst = out + (size_t)m * (S_DIM * S_DIM);
    #pragma unroll
    for (int p = 0; p < 4; p++) {
        int i0 = ti * 8 + 2 * p;
        float2 c0 = unpack2(acc[p][0]), c1 = unpack2(acc[p][1]);
        float2 c2 = unpack2(acc[p][2]), c3 = unpack2(acc[p][3]);
        *reinterpret_cast<float4*>(&dst[i0 * S_DIM + tj * 4]) =
            make_float4(c0.x, c1.x, c2.x, c3.x);
        *reinterpret_cast<float4*>(&dst[(i0 + 1) * S_DIM + tj * 4]) =
            make_float4(c0.y, c1.y, c2.y, c3.y);
    }
}

extern "C" void kernel_launch(void* const* d_in, const int* in_sizes, int n_in,
                              void* d_out, int out_size)
{
    const float* x = (const float*)d_in[0];   // [B, C, 32, 32] fp32
    const float* H = (const float*)d_in[1];   // [32, 32] fp32
    float* out = (float*)d_out;

    int nMat = in_sizes[0] / (S_DIM * S_DIM); // 65536
    int blocks = (nMat + MATS_PER_BLOCK - 1) / MATS_PER_BLOCK;

    dct2d_kernel<<<blocks, NTHREADS>>>(x, H, out, nMat);
}

// round 5
// speedup vs baseline: 1.2085x; 1.2085x over previous
#include <cuda_runtime.h>

// out[b,c] = H @ x[b,c] @ H^T for 65536 independent 32x32 fp32 matrices.
// One warp per matrix. f32x2-packed 8x4 register tile (row pairs) PLUS the
// DCT even/odd butterfly: H[i][31-k] = (-1)^i H[i][k], so each 32-term
// contraction folds to 16 terms over E=Xk+X(31-k) (even rows) and
// O=Xk-X(31-k) (odd rows). The (even,odd) row-pair accumulators consume the
// packed (E,O) pair directly -> half the k-steps at the same fma2/step.

#define S_DIM 32
#define STRIDE 36              // 32 + 4 pad floats: 16B-aligned, conflict-free
#define WARPS_PER_BLOCK 8
#define MATS_PER_BLOCK WARPS_PER_BLOCK
#define NTHREADS (WARPS_PER_BLOCK * 32)

typedef unsigned long long u64;

__device__ __forceinline__ void fma2(u64& d, u64 a, u64 b) {
    asm("fma.rn.f32x2 %0, %1, %2, %0;" : "+l"(d) : "l"(a), "l"(b));
}
// d = a*b + c
__device__ __forceinline__ u64 fma2v(u64 a, u64 b, u64 c) {
    u64 d;
    asm("fma.rn.f32x2 %0, %1, %2, %3;" : "=l"(d) : "l"(a), "l"(b), "l"(c));
    return d;
}
__device__ __forceinline__ u64 add2(u64 a, u64 b) {
    u64 d;
    asm("add.rn.f32x2 %0, %1, %2;" : "=l"(d) : "l"(a), "l"(b));
    return d;
}
__device__ __forceinline__ u64 splat2(float v) {
    u64 r;
    asm("mov.b64 %0, {%1, %1};" : "=l"(r) : "f"(v));
    return r;
}
__device__ __forceinline__ u64 pack2(float lo, float hi) {
    u64 r;
    asm("mov.b64 %0, {%1, %2};" : "=l"(r) : "f"(lo), "f"(hi));
    return r;
}
__device__ __forceinline__ float2 unpack2(u64 u) {
    float2 f;
    asm("mov.b64 {%0, %1}, %2;" : "=f"(f.x), "=f"(f.y) : "l"(u));
    return f;
}

#define NEG1_X2 0xBF800000BF800000ULL   // (-1.0f, -1.0f)

__global__ __launch_bounds__(NTHREADS, 3)
void dct2d_kernel(const float* __restrict__ x,
                  const float* __restrict__ H,
                  float* __restrict__ out,
                  int nMat)
{
    // Ht16[k][i] = H[i][k] for k < 16 only (butterfly uses low-k rows).
    __shared__ __align__(16) float Ht16[16 * S_DIM];
    __shared__ __align__(16) float buf[MATS_PER_BLOCK][S_DIM * STRIDE];  // X, then T^T

    const int tid = threadIdx.x;

    // Build Ht16 once per block: 512 entries.
    #pragma unroll
    for (int e = tid; e < 16 * S_DIM; e += NTHREADS) {
        int k = e >> 5;          // 0..15
        int i = e & 31;          // 0..31
        Ht16[k * S_DIM + i] = H[i * S_DIM + k];
    }
    __syncthreads();

    const int warp = tid >> 5;
    const int lane = tid & 31;
    const int m = blockIdx.x * WARPS_PER_BLOCK + warp;
    if (m >= nMat) return;

    float* Xs = buf[warp];
    const float4* __restrict__ src =
        reinterpret_cast<const float4*>(x + (size_t)m * (S_DIM * S_DIM));

    // ---- load X[32][32] into padded smem (coalesced float4) ----
    #pragma unroll
    for (int q = 0; q < 8; q++) {
        int f   = lane + 32 * q;
        int row = f >> 3;
        int c4  = f & 7;
        *reinterpret_cast<float4*>(&Xs[row * STRIDE + c4 * 4]) = src[f];
    }
    __syncwarp();

    const int ti = lane >> 3;   // rows ti*8 .. ti*8+7
    const int tj = lane & 7;    // cols tj*4 .. tj*4+3

    // acc[p][c] packs rows (ti*8+2p [even], ti*8+2p+1 [odd]) at col tj*4+c
    u64 acc[4][4];
    #pragma unroll
    for (int p = 0; p < 4; p++)
        #pragma unroll
        for (int c = 0; c < 4; c++) acc[p][c] = 0ull;

    // ---- stage 1: T[i][j] = sum_{k<16} H[i][k] * (i even ? E : O)[k][j]
    //      E[k][j] = X[k][j] + X[31-k][j],  O[k][j] = X[k][j] - X[31-k][j]
    #pragma unroll 8
    for (int k = 0; k < 16; k++) {
        const ulonglong2* ap =
            reinterpret_cast<const ulonglong2*>(&Ht16[k * S_DIM + ti * 8]);
        ulonglong2 aA = ap[0], aB = ap[1];
        u64 a[4] = {aA.x, aA.y, aB.x, aB.y};

        // b rows k and 31-k as f32x2 pairs (cols tj*4..tj*4+3)
        ulonglong2 bk = *reinterpret_cast<const ulonglong2*>(&Xs[k * STRIDE + tj * 4]);
        ulonglong2 br = *reinterpret_cast<const ulonglong2*>(&Xs[(31 - k) * STRIDE + tj * 4]);
        u64 e01 = add2(bk.x, br.x);                 // (E_c0, E_c1)
        u64 e23 = add2(bk.y, br.y);                 // (E_c2, E_c3)
        u64 o01 = fma2v(br.x, NEG1_X2, bk.x);       // (O_c0, O_c1)
        u64 o23 = fma2v(br.y, NEG1_X2, bk.y);

        float2 ef = unpack2(e01), of = unpack2(o01);
        float2 eg = unpack2(e23), og = unpack2(o23);
        u64 eo[4] = { pack2(ef.x, of.x), pack2(ef.y, of.y),
                      pack2(eg.x, og.x), pack2(eg.y, og.y) };

        #pragma unroll
        for (int p = 0; p < 4; p++)
            #pragma unroll
            for (int c = 0; c < 4; c++)
                fma2(acc[p][c], a[p], eo[c]);
    }
    __syncwarp();

    // ---- write T transposed back: Tt[j][i] = T[i][j] ----
    #pragma unroll
    for (int c = 0; c < 4; c++) {
        int row = tj * 4 + c;
        float2 f0 = unpack2(acc[0][c]), f1 = unpack2(acc[1][c]);
        float2 f2 = unpack2(acc[2][c]), f3 = unpack2(acc[3][c]);
        *reinterpret_cast<float4*>(&Xs[row * STRIDE + ti * 8]) =
            make_float4(f0.x, f0.y, f1.x, f1.y);
        *reinterpret_cast<float4*>(&Xs[row * STRIDE + ti * 8 + 4]) =
            make_float4(f2.x, f2.y, f3.x, f3.y);
    }
    __syncwarp();

    #pragma unroll
    for (int p = 0; p < 4; p++)
        #pragma unroll
        for (int c = 0; c < 4; c++) acc[p][c] = 0ull;

    // ---- stage 2: Out[i][l] = sum_{j<16} H[l][j] * (l even ? E2 : O2)[i][j]
    //      E2[i][j] = Tt[j][i] + Tt[31-j][i],  O2[i][j] = Tt[j][i] - Tt[31-j][i]
    //      E2/O2 pairs along i come directly from the a-side f32x2 pairs;
    //      parity of l = tj*4+c is the parity of c.
    #pragma unroll 8
    for (int k = 0; k < 16; k++) {
        const ulonglong2* akp =
            reinterpret_cast<const ulonglong2*>(&Xs[k * STRIDE + ti * 8]);
        const ulonglong2* arp =
            reinterpret_cast<const ulonglong2*>(&Xs[(31 - k) * STRIDE + ti * 8]);
        ulonglong2 akA = akp[0], akB = akp[1];
        ulonglong2 arA = arp[0], arB = arp[1];
        u64 ak[4] = {akA.x, akA.y, akB.x, akB.y};
        u64 ar[4] = {arA.x, arA.y, arB.x, arB.y};

        u64 E[4], O[4];
        #pragma unroll
        for (int p = 0; p < 4; p++) {
            E[p] = add2(ak[p], ar[p]);
            O[p] = fma2v(ar[p], NEG1_X2, ak[p]);
        }

        float4 b4 = *reinterpret_cast<const float4*>(&Ht16[k * S_DIM + tj * 4]);
        u64 bb[4] = {splat2(b4.x), splat2(b4.y), splat2(b4.z), splat2(b4.w)};

        #pragma unroll
        for (int p = 0; p < 4; p++) {
            fma2(acc[p][0], E[p], bb[0]);   // c=0: l even -> E
            fma2(acc[p][1], O[p], bb[1]);   // c=1: l odd  -> O
            fma2(acc[p][2], E[p], bb[2]);   // c=2: even
            fma2(acc[p][3], O[p], bb[3]);   // c=3: odd
        }
    }

    // ---- store Out[32][32] (coalesced float4) ----
    float* __restrict__ dst = out + (size_t)m * (S_DIM * S_DIM);
    #pragma unroll
    for (int p = 0; p < 4; p++) {
        int i0 = ti * 8 + 2 * p;
        float2 c0 = unpack2(acc[p][0]), c1 = unpack2(acc[p][1]);
        float2 c2 = unpack2(acc[p][2]), c3 = unpack2(acc[p][3]);
        *reinterpret_cast<float4*>(&dst[i0 * S_DIM + tj * 4]) =
            make_float4(c0.x, c1.x, c2.x, c3.x);
        *reinterpret_cast<float4*>(&dst[(i0 + 1) * S_DIM + tj * 4]) =
            make_float4(c0.y, c1.y, c2.y, c3.y);
    }
}

extern "C" void kernel_launch(void* const* d_in, const int* in_sizes, int n_in,
                              void* d_out, int out_size)
{
    const float* x = (const float*)d_in[0];   // [B, C, 32, 32] fp32
    const float* H = (const float*)d_in[1];   // [32, 32] fp32
    float* out = (float*)d_out;

    int nMat = in_sizes[0] / (S_DIM * S_DIM); // 65536
    int blocks = (nMat + MATS_PER_BLOCK - 1) / MATS_PER_BLOCK;

    dct2d_kernel<<<blocks, NTHREADS>>>(x, H, out, nMat);
}